// round 1
// baseline (speedup 1.0000x reference)
#include <cuda_runtime.h>
#include <math.h>

#define D 32
#define H 128
#define NB 128
#define NSTEPS 8
#define DT (1.0f/8.0f)
#define LOG2PI 1.837877066409345483560659472811f

// padded shared-memory row strides (floats) for bank-conflict-free float4 LDS
#define W1S 36
#define W2S 132
#define W3S 132
#define KS 36

// E[m*H+k] = W2[m,k] * (W1 @ W3)[k,m]   (input-independent per launch)
__device__ float g_E[H * H];

__constant__ float c_a[6][5] = {
    {0.f, 0.f, 0.f, 0.f, 0.f},
    {0.2f, 0.f, 0.f, 0.f, 0.f},
    {3.f/40.f, 9.f/40.f, 0.f, 0.f, 0.f},
    {44.f/45.f, -56.f/15.f, 32.f/9.f, 0.f, 0.f},
    {19372.f/6561.f, -25360.f/2187.f, 64448.f/6561.f, -212.f/729.f, 0.f},
    {9017.f/3168.f, -355.f/33.f, 46732.f/5247.f, 49.f/176.f, -5103.f/18656.f}
};
__constant__ float c_c[6] = {0.f, 0.2f, 0.3f, 0.8f, 8.f/9.f, 1.f};

__global__ void precompute_E_kernel(const float* __restrict__ W1,
                                    const float* __restrict__ W2,
                                    const float* __restrict__ W3) {
    __shared__ float sW1[H * D];
    __shared__ float sw3col[D];
    int m = blockIdx.x;
    int k = threadIdx.x;
    for (int idx = k; idx < H * D; idx += H) sW1[idx] = W1[idx];
    if (k < D) sw3col[k] = W3[k * H + m];
    __syncthreads();
    float acc = 0.f;
#pragma unroll
    for (int j = 0; j < D; j++) acc += sW1[k * D + j] * sw3col[j];
    g_E[m * H + k] = W2[m * H + k] * acc;
}

// shared memory layout size (floats)
#define SMEM_FLOATS (H*W1S + 2*H*W2S + D*W3S + 3*H + 2*D + 3*H + D + KS + 6*KS + H + 8)
#define SMEM_BYTES (SMEM_FLOATS * 4)

__global__ __launch_bounds__(H, 1)
void ode_kernel(const float* __restrict__ x0,
                const float* __restrict__ W1g,
                const float* __restrict__ u1,
                const float* __restrict__ b1,
                const float* __restrict__ W2g,
                const float* __restrict__ b2,
                const float* __restrict__ W3g,
                const float* __restrict__ b3,
                const float* __restrict__ prec,
                float* __restrict__ out)
{
    extern __shared__ float smp[];
    float* sW1   = smp;                    // H*W1S
    float* sW2   = sW1 + H*W1S;            // H*W2S
    float* sE    = sW2 + H*W2S;            // H*W2S
    float* sW3   = sE  + H*W2S;            // D*W3S
    float* su1   = sW3 + D*W3S;            // H
    float* sb1   = su1 + H;                // H
    float* sb2   = sb1 + H;                // H
    float* sb3   = sb2 + H;                // D
    float* sprec = sb3 + D;                // D
    float* sh1   = sprec + D;              // H
    float* sd1   = sh1 + H;                // H
    float* sh2   = sd1 + H;                // H
    float* sx    = sh2 + H;                // D
    float* sy    = sx + D;                 // KS (34 used)
    float* sk    = sy + KS;                // 6*KS
    float* sred  = sk + 6*KS;              // H
    float* strce = sred + H;               // 4 (+pad)

    const int tid  = threadIdx.x;
    const int lane = tid & 31;
    const int wid  = tid >> 5;
    const int b    = blockIdx.x;

    // ---- load weights into padded smem ----
#pragma unroll 4
    for (int idx = tid; idx < H*H; idx += H) {
        int r = idx >> 7, c = idx & 127;
        sW2[r*W2S + c] = W2g[idx];
        sE [r*W2S + c] = g_E[idx];
    }
#pragma unroll
    for (int idx = tid; idx < H*D; idx += H) {
        int r = idx >> 5, c = idx & 31;
        sW1[r*W1S + c] = W1g[idx];
    }
#pragma unroll
    for (int idx = tid; idx < D*H; idx += H) {
        int r = idx >> 7, c = idx & 127;
        sW3[r*W3S + c] = W3g[idx];
    }
    su1[tid] = u1[tid];
    sb1[tid] = b1[tid];
    sb2[tid] = b2[tid];
    if (tid < D) { sb3[tid] = b3[tid]; sprec[tid] = prec[tid]; }
    if (tid < D) sy[tid] = x0[b*D + tid];
    if (tid == D || tid == D+1) sy[tid] = 0.f;
    __syncthreads();

    for (int step = 0; step < NSTEPS; step++) {
        const float t0 = (float)step * DT;
        for (int s = 0; s < 6; s++) {
            // stage state x_s = y + dt * sum_l a[s][l] * k_l   (x components only)
            if (tid < D) {
                float v = sy[tid];
                for (int l = 0; l < s; l++)
                    v += DT * c_a[s][l] * sk[l*KS + tid];
                sx[tid] = v;
            }
            __syncthreads();
            const float t = t0 + c_c[s] * DT;

            // ---- layer 1: h1 = tanh(W1 x + t u1 + b1) ----
            {
                float a0=0.f,a1=0.f,a2=0.f,a3=0.f;
                const float4* wr = (const float4*)(sW1 + tid*W1S);
                const float4* xv = (const float4*)sx;
#pragma unroll
                for (int c = 0; c < D/4; c++) {
                    float4 w = wr[c], x4 = xv[c];
                    a0 += w.x*x4.x; a1 += w.y*x4.y; a2 += w.z*x4.z; a3 += w.w*x4.w;
                }
                float z = (a0+a1)+(a2+a3) + t*su1[tid] + sb1[tid];
                float h = tanhf(z);
                sh1[tid] = h;
                sd1[tid] = 1.f - h*h;
            }
            __syncthreads();

            // ---- layer 2 (W2 @ h1) fused with E @ d1 (trace) ----
            {
                float a0=0.f,a1=0.f,a2=0.f,a3=0.f;
                float g0=0.f,g1=0.f,g2=0.f,g3=0.f;
                const float4* wr = (const float4*)(sW2 + tid*W2S);
                const float4* er = (const float4*)(sE  + tid*W2S);
                const float4* hv = (const float4*)sh1;
                const float4* dv = (const float4*)sd1;
#pragma unroll 8
                for (int c = 0; c < H/4; c++) {
                    float4 w = wr[c], h4 = hv[c];
                    a0 += w.x*h4.x; a1 += w.y*h4.y; a2 += w.z*h4.z; a3 += w.w*h4.w;
                    float4 e = er[c], d4 = dv[c];
                    g0 += e.x*d4.x; g1 += e.y*d4.y; g2 += e.z*d4.z; g3 += e.w*d4.w;
                }
                float z = (a0+a1)+(a2+a3) + sb2[tid];
                float h = tanhf(z);
                sh2[tid] = h;
                float d2v = 1.f - h*h;
                float tr = d2v * ((g0+g1)+(g2+g3));
#pragma unroll
                for (int off = 16; off; off >>= 1)
                    tr += __shfl_xor_sync(0xffffffffu, tr, off);
                if (lane == 0) strce[wid] = tr;
            }
            __syncthreads();

            // ---- layer 3 partials: thread (lane, wid) does cols [wid*32, wid*32+32) of row=lane ----
            {
                float a0=0.f,a1=0.f,a2=0.f,a3=0.f;
                const float4* wr = (const float4*)(sW3 + lane*W3S + wid*32);
                const float4* hv = (const float4*)(sh2 + wid*32);
#pragma unroll
                for (int c = 0; c < 8; c++) {
                    float4 w = wr[c], h4 = hv[c];
                    a0 += w.x*h4.x; a1 += w.y*h4.y; a2 += w.z*h4.z; a3 += w.w*h4.w;
                }
                sred[wid*32 + lane] = (a0+a1)+(a2+a3);
            }
            __syncthreads();

            // ---- finalize (warp 0): o, k vector, dkl / dlogp scalars ----
            if (wid == 0) {
                float o = sred[lane] + sred[32+lane] + sred[64+lane] + sred[96+lane] + sb3[lane];
                float* kout = sk + s*KS;
                kout[lane] = o;
                float xs = sx[lane];
                float lp = -0.5f*xs*xs - 0.5f*LOG2PI;
                float gl = -sprec[lane]*xs;
                float d1dot = lp * o;
                float d2dot = gl * o;
#pragma unroll
                for (int off = 16; off; off >>= 1) {
                    d1dot += __shfl_xor_sync(0xffffffffu, d1dot, off);
                    d2dot += __shfl_xor_sync(0xffffffffu, d2dot, off);
                }
                if (lane == 0) {
                    float trace = strce[0]+strce[1]+strce[2]+strce[3];
                    float dlp = -trace;
                    float omt = 1.f - t;
                    float dkl = -0.5f*omt*omt*d1dot - 0.5f*omt*(1.f+t)*d2dot + omt*dlp;
                    kout[D]   = dlp;
                    kout[D+1] = dkl;
                }
            }
            __syncthreads();
        }
        // ---- dopri5 5th-order combine (b2 = 0) ----
        if (tid < D+2) {
            sy[tid] += DT * ( (35.f/384.f)    * sk[0*KS+tid]
                            + (500.f/1113.f)  * sk[2*KS+tid]
                            + (125.f/192.f)   * sk[3*KS+tid]
                            - (2187.f/6784.f) * sk[4*KS+tid]
                            + (11.f/84.f)     * sk[5*KS+tid] );
        }
        __syncthreads();
    }

    // ---- epilogue: z, log_px0 + log_det, kl ----
    if (wid == 0) {
        float z = sy[lane];
        out[b*D + lane] = z;
        float xv = x0[b*D + lane];
        float lp = -0.5f*xv*xv - 0.5f*LOG2PI;
#pragma unroll
        for (int off = 16; off; off >>= 1)
            lp += __shfl_xor_sync(0xffffffffu, lp, off);
        if (lane == 0) {
            out[NB*D + b]      = lp + sy[D];
            out[NB*D + NB + b] = sy[D+1];
        }
    }
}

extern "C" void kernel_launch(void* const* d_in, const int* in_sizes, int n_in,
                              void* d_out, int out_size) {
    const float* x0   = (const float*)d_in[0];
    const float* W1   = (const float*)d_in[1];
    const float* u1   = (const float*)d_in[2];
    const float* b1   = (const float*)d_in[3];
    const float* W2   = (const float*)d_in[4];
    const float* b2   = (const float*)d_in[5];
    const float* W3   = (const float*)d_in[6];
    const float* b3   = (const float*)d_in[7];
    const float* prec = (const float*)d_in[8];
    float* out = (float*)d_out;

    cudaFuncSetAttribute(ode_kernel, cudaFuncAttributeMaxDynamicSharedMemorySize, SMEM_BYTES);

    precompute_E_kernel<<<H, H>>>(W1, W2, W3);
    ode_kernel<<<NB, H, SMEM_BYTES>>>(x0, W1, u1, b1, W2, b2, W3, b3, prec, out);
}

// round 3
// speedup vs baseline: 2.3798x; 2.3798x over previous
#include <cuda_runtime.h>
#include <math.h>

#define D 32
#define H 128
#define NB 128
#define NSTEPS 8
#define DTf 0.125f
#define LOG2PI 1.837877066409345483560659472811f

// E[m*H+k] = W2[m,k] * (W1 @ W3)[k,m]   (input-independent)
__device__ float g_E[H * H];

// dopri5 tableau (compile-time folded in unrolled stage loop)
static __device__ constexpr float Aa[6][5] = {
    {0.f, 0.f, 0.f, 0.f, 0.f},
    {0.2f, 0.f, 0.f, 0.f, 0.f},
    {3.f/40.f, 9.f/40.f, 0.f, 0.f, 0.f},
    {44.f/45.f, -56.f/15.f, 32.f/9.f, 0.f, 0.f},
    {19372.f/6561.f, -25360.f/2187.f, 64448.f/6561.f, -212.f/729.f, 0.f},
    {9017.f/3168.f, -355.f/33.f, 46732.f/5247.f, 49.f/176.f, -5103.f/18656.f}
};
static __device__ constexpr float Bb[6] = {
    35.f/384.f, 0.f, 500.f/1113.f, 125.f/192.f, -2187.f/6784.f, 11.f/84.f
};
static __device__ constexpr float Cc[6] = {0.f, 0.2f, 0.3f, 0.8f, 8.f/9.f, 1.f};

__global__ void precompute_E_kernel(const float* __restrict__ W1,
                                    const float* __restrict__ W2,
                                    const float* __restrict__ W3) {
    __shared__ float sW1[H * D];
    __shared__ float sw3col[D];
    int m = blockIdx.x;
    int k = threadIdx.x;
    for (int idx = k; idx < H * D; idx += H) sW1[idx] = W1[idx];
    if (k < D) sw3col[k] = W3[k * H + m];
    __syncthreads();
    float acc = 0.f;
#pragma unroll
    for (int j = 0; j < D; j++) acc += sW1[k * D + j] * sw3col[j];
    g_E[m * H + k] = W2[m * H + k] * acc;
}

__device__ __forceinline__ float ftanh(float z) {
    float e = __expf(2.f * z);
    return 1.f - __fdividef(2.f, e + 1.f);
}

__global__ __launch_bounds__(256, 1)
void ode_kernel(const float* __restrict__ x0,
                const float* __restrict__ W1g,
                const float* __restrict__ u1g,
                const float* __restrict__ b1g,
                const float* __restrict__ W2g,
                const float* __restrict__ b2g,
                const float* __restrict__ W3g,
                const float* __restrict__ b3g,
                const float* __restrict__ precg,
                float* __restrict__ out)
{
    __shared__ __align__(16) float sx[D];       // current stage state
    __shared__ __align__(16) float sy[D];       // integrated state
    __shared__ __align__(16) float sh1[H];
    __shared__ __align__(16) float sh2[H];
    __shared__ __align__(16) float skv[6][D];   // stage k vectors (x comps)
    __shared__ float sp1[NSTEPS * 6 * D];       // lp(xs)*o per (stage,row)
    __shared__ float sp2[NSTEPS * 6 * D];       // gradlog(xs)*o
    __shared__ float strc[NSTEPS * 6 * 8];      // trace partial per (stage,warp)
    __shared__ float sfin[16];

    const int tid  = threadIdx.x;
    const int lane = tid & 31;
    const int wid  = tid >> 5;
    const int r2   = tid >> 1;   // hidden row (pair)
    const int half = tid & 1;    // which K-half
    const int r3   = tid >> 3;   // output row (group of 8)
    const int sub  = tid & 7;
    const int b    = blockIdx.x;

    // ---- register-resident weights ----
    float4 W1h[4], W2h[16], Eh[16], W3c[4];
    {
        const float4* p = (const float4*)(W1g + r2 * D + half * 16);
#pragma unroll
        for (int i = 0; i < 4; i++) W1h[i] = p[i];
        const float4* q = (const float4*)(W2g + r2 * H + half * 64);
        const float4* e = (const float4*)(g_E + r2 * H + half * 64);
#pragma unroll
        for (int i = 0; i < 16; i++) { W2h[i] = q[i]; Eh[i] = e[i]; }
        const float4* w3 = (const float4*)(W3g + r3 * H + sub * 16);
#pragma unroll
        for (int i = 0; i < 4; i++) W3c[i] = w3[i];
    }
    const float u1r = u1g[r2];
    const float b1r = b1g[r2];
    const float b2r = b2g[r2];
    const float b3r = b3g[r3];
    const float prr = precg[r3];

    if (tid < D) { float v = x0[b * D + tid]; sy[tid] = v; sx[tid] = v; }
    __syncthreads();

#pragma unroll 1
    for (int step = 0; step < NSTEPS; step++) {
        const float t0 = (float)step * DTf;
#pragma unroll
        for (int s = 0; s < 6; s++) {
            const float t = t0 + Cc[s] * DTf;

            // ---- layer 1: h1 = tanh(W1 x + t u1 + b1), pair-split K ----
            {
                const float4* xv = ((const float4*)sx) + half * 4;
                float a0 = 0.f, a1 = 0.f, a2 = 0.f, a3 = 0.f;
#pragma unroll
                for (int c = 0; c < 4; c++) {
                    float4 w = W1h[c], x4 = xv[c];
                    a0 = fmaf(w.x, x4.x, a0); a1 = fmaf(w.y, x4.y, a1);
                    a2 = fmaf(w.z, x4.z, a2); a3 = fmaf(w.w, x4.w, a3);
                }
                float p = (a0 + a1) + (a2 + a3);
                p += __shfl_xor_sync(0xffffffffu, p, 1);
                float h = ftanh(p + t * u1r + b1r);
                if (!half) sh1[r2] = h;
            }
            __syncthreads();

            // ---- layer 2 (W2 h1) fused with trace (E (1-h1^2)) ----
            {
                const float4* hv = ((const float4*)sh1) + half * 16;
                float a0 = 0.f, a1 = 0.f, a2 = 0.f, a3 = 0.f;
                float g0 = 0.f, g1 = 0.f, g2 = 0.f, g3 = 0.f;
#pragma unroll
                for (int c = 0; c < 16; c++) {
                    float4 h4 = hv[c];
                    float4 w = W2h[c], e = Eh[c];
                    a0 = fmaf(w.x, h4.x, a0); a1 = fmaf(w.y, h4.y, a1);
                    a2 = fmaf(w.z, h4.z, a2); a3 = fmaf(w.w, h4.w, a3);
                    float d0 = fmaf(-h4.x, h4.x, 1.f);
                    float d1 = fmaf(-h4.y, h4.y, 1.f);
                    float d2 = fmaf(-h4.z, h4.z, 1.f);
                    float d3 = fmaf(-h4.w, h4.w, 1.f);
                    g0 = fmaf(e.x, d0, g0); g1 = fmaf(e.y, d1, g1);
                    g2 = fmaf(e.z, d2, g2); g3 = fmaf(e.w, d3, g3);
                }
                float pz = (a0 + a1) + (a2 + a3);
                pz += __shfl_xor_sync(0xffffffffu, pz, 1);
                float h2 = ftanh(pz + b2r);
                if (!half) sh2[r2] = h2;
                float tr = fmaf(-h2, h2, 1.f) * ((g0 + g1) + (g2 + g3));
#pragma unroll
                for (int o = 16; o; o >>= 1)
                    tr += __shfl_xor_sync(0xffffffffu, tr, o);
                if (lane == 0) strc[(step * 6 + s) * 8 + wid] = tr;
            }
            __syncthreads();

            // ---- layer 3 (8 threads per output row) + inline next-x ----
            {
                const float4* hv = ((const float4*)sh2) + sub * 4;
                float a0 = 0.f, a1 = 0.f, a2 = 0.f, a3 = 0.f;
#pragma unroll
                for (int c = 0; c < 4; c++) {
                    float4 w = W3c[c], h4 = hv[c];
                    a0 = fmaf(w.x, h4.x, a0); a1 = fmaf(w.y, h4.y, a1);
                    a2 = fmaf(w.z, h4.z, a2); a3 = fmaf(w.w, h4.w, a3);
                }
                float o = (a0 + a1) + (a2 + a3);
                o += __shfl_xor_sync(0xffffffffu, o, 1);
                o += __shfl_xor_sync(0xffffffffu, o, 2);
                o += __shfl_xor_sync(0xffffffffu, o, 4);
                if (sub == 0) {
                    o += b3r;
                    skv[s][r3] = o;
                    float xs = sx[r3];
                    int idx = (step * 6 + s) * D + r3;
                    sp1[idx] = (-0.5f * xs * xs - 0.5f * LOG2PI) * o;
                    sp2[idx] = (-prr * xs) * o;
                    float yv = sy[r3];
                    float xn;
                    if (s < 5) {
                        float acc = Aa[s + 1][s] * o;
#pragma unroll
                        for (int l = 0; l < s; l++)
                            acc += Aa[s + 1][l] * skv[l][r3];
                        xn = yv + DTf * acc;
                    } else {
                        float acc = Bb[0] * skv[0][r3] + Bb[2] * skv[2][r3]
                                  + Bb[3] * skv[3][r3] + Bb[4] * skv[4][r3]
                                  + Bb[5] * o;
                        xn = yv + DTf * acc;
                        sy[r3] = xn;
                    }
                    sx[r3] = xn;
                }
            }
            __syncthreads();
        }
    }

    // ---- epilogue: warp w reduces step w's 6 stages (dkl / dlogp deferred) ----
    {
        float ldw = 0.f, klw = 0.f;
        const int stp = wid;
#pragma unroll
        for (int s = 0; s < 6; s++) {
            if (s == 1) continue;  // Bb[1] == 0
            int idx = stp * 6 + s;
            float v1 = sp1[idx * D + lane];
            float v2 = sp2[idx * D + lane];
            float v3 = (lane < 8) ? strc[idx * 8 + lane] : 0.f;
#pragma unroll
            for (int o = 16; o; o >>= 1) {
                v1 += __shfl_xor_sync(0xffffffffu, v1, o);
                v2 += __shfl_xor_sync(0xffffffffu, v2, o);
                v3 += __shfl_xor_sync(0xffffffffu, v3, o);
            }
            float t = (float)stp * DTf + Cc[s] * DTf;
            float omt = 1.f - t;
            float dlp = -v3;
            float dkl = -0.5f * omt * omt * v1
                        - 0.5f * omt * (1.f + t) * v2
                        + omt * dlp;
            ldw += Bb[s] * dlp;
            klw += Bb[s] * dkl;
        }
        if (lane == 0) { sfin[stp] = ldw; sfin[8 + stp] = klw; }
    }
    // z output (warp 1; sy final after last barrier in the loop)
    if (wid == 1) out[b * D + lane] = sy[lane];
    __syncthreads();

    if (wid == 0) {
        float a = (lane < 8) ? sfin[lane] : 0.f;
        float k = (lane < 8) ? sfin[8 + lane] : 0.f;
        float xv = x0[b * D + lane];
        float lp = -0.5f * xv * xv - 0.5f * LOG2PI;
#pragma unroll
        for (int o = 16; o; o >>= 1) {
            a  += __shfl_xor_sync(0xffffffffu, a, o);
            k  += __shfl_xor_sync(0xffffffffu, k, o);
            lp += __shfl_xor_sync(0xffffffffu, lp, o);
        }
        if (lane == 0) {
            out[NB * D + b]      = lp + DTf * a;
            out[NB * D + NB + b] = DTf * k;
        }
    }
}

extern "C" void kernel_launch(void* const* d_in, const int* in_sizes, int n_in,
                              void* d_out, int out_size) {
    const float* x0   = (const float*)d_in[0];
    const float* W1   = (const float*)d_in[1];
    const float* u1   = (const float*)d_in[2];
    const float* b1   = (const float*)d_in[3];
    const float* W2   = (const float*)d_in[4];
    const float* b2   = (const float*)d_in[5];
    const float* W3   = (const float*)d_in[6];
    const float* b3   = (const float*)d_in[7];
    const float* prec = (const float*)d_in[8];
    float* out = (float*)d_out;

    precompute_E_kernel<<<H, H>>>(W1, W2, W3);
    ode_kernel<<<NB, 256>>>(x0, W1, u1, b1, W2, b2, W3, b3, prec, out);
}